// round 5
// baseline (speedup 1.0000x reference)
#include <cuda_runtime.h>
#include <math.h>

// Problem constants
#define Bc 8
#define Tc 1024
#define Ec 1024
#define Hc 16
#define Dc 64
#define Mc (Bc * Tc)          // 8192
#define NREL (2 * Tc - 1)     // 2047

// Scratch (static device globals; no cudaMalloc allowed)
__device__ float g_q[(size_t)Bc * Hc * Tc * Dc];   // [B,H,T,D]
__device__ float g_k[(size_t)Bc * Hc * Tc * Dc];
__device__ float g_v[(size_t)Bc * Hc * Tc * Dc];
__device__ float g_ao[(size_t)Bc * Hc * Tc * Dc];  // attention output [B,H,T,D]
__device__ float g_bias[Hc * NREL];                // bias_rel[h][r]

// ---------------------------------------------------------------------------
// Kernel 1: precompute interpolated relative bias per (h, rel)
// ---------------------------------------------------------------------------
__global__ void bias_kernel(const float* __restrict__ table,  // [2T-1, H]
                            const float* __restrict__ offset) {
    float bounded = tanhf(offset[0]) * 0.5f;
    for (int idx = blockIdx.x * blockDim.x + threadIdx.x; idx < Hc * NREL;
         idx += gridDim.x * blockDim.x) {
        int h = idx / NREL;
        int r = idx - h * NREL;
        float adj = (float)r + bounded;
        adj = fminf(fmaxf(adj, 0.0f), (float)(NREL - 1));
        int lo = (int)floorf(adj);
        int hi = (int)ceilf(adj);
        float w = adj - (float)lo;
        float lov = table[lo * Hc + h];
        float hiv = table[hi * Hc + h];
        g_bias[h * NREL + r] = lov * (1.0f - w) + hiv * w;
    }
}

// ---------------------------------------------------------------------------
// Kernel 2: NT GEMM  C[M,N] = A[M,K] * W[N,K]^T + bias[N]
//   IN_HEADS : gather A from g_ao laid out [B,H,T,D] (head-merge)
//   OUT_QKV  : scatter C into [B,H,T,D] (head-split), sel picks g_q/g_k/g_v
// M=8192, N=K=1024.  Tiles: 128x128x8, 256 threads, 8x8 per thread (4x4 quads)
// ---------------------------------------------------------------------------
template <int IN_HEADS, int OUT_QKV>
__global__ __launch_bounds__(256) void gemm_nt(const float* __restrict__ A,
                                               const float* __restrict__ W,
                                               const float* __restrict__ bias,
                                               float* __restrict__ Cplain,
                                               int sel) {
    __shared__ float As[8][128];
    __shared__ float Ws[8][128];

    const int tid = threadIdx.x;
    const int m0 = blockIdx.y * 128;
    const int n0 = blockIdx.x * 128;
    const int tr = tid >> 4;       // 0..15
    const int tc = tid & 15;       // 0..15
    const int lrow = tid >> 1;     // 0..127
    const int lcol = (tid & 1) * 4;

    const float* Ain = IN_HEADS ? g_ao : A;
    float* C;
    if (OUT_QKV) {
        C = (sel == 0) ? g_q : ((sel == 1) ? g_k : g_v);
    } else {
        C = Cplain;
    }

    float acc[8][8];
#pragma unroll
    for (int x = 0; x < 8; x++)
#pragma unroll
        for (int y = 0; y < 8; y++) acc[x][y] = 0.0f;

    for (int kt = 0; kt < Ec; kt += 8) {
        float4 av, wv;
        {
            int m = m0 + lrow;
            int k = kt + lcol;
            const float* src;
            if (IN_HEADS) {
                int b = m >> 10, t = m & 1023;
                int h = k >> 6, d = k & 63;
                src = Ain + (((size_t)(b * Hc + h) * Tc + t) * Dc + d);
            } else {
                src = Ain + (size_t)m * Ec + k;
            }
            av = *(const float4*)src;
            wv = *(const float4*)(W + (size_t)(n0 + lrow) * Ec + k);
        }
        __syncthreads();
        As[lcol + 0][lrow] = av.x;
        As[lcol + 1][lrow] = av.y;
        As[lcol + 2][lrow] = av.z;
        As[lcol + 3][lrow] = av.w;
        Ws[lcol + 0][lrow] = wv.x;
        Ws[lcol + 1][lrow] = wv.y;
        Ws[lcol + 2][lrow] = wv.z;
        Ws[lcol + 3][lrow] = wv.w;
        __syncthreads();

#pragma unroll
        for (int k = 0; k < 8; k++) {
            float a[8], b[8];
            float4 t0 = *(const float4*)&As[k][tr * 4];
            float4 t1 = *(const float4*)&As[k][tr * 4 + 64];
            float4 t2 = *(const float4*)&Ws[k][tc * 4];
            float4 t3 = *(const float4*)&Ws[k][tc * 4 + 64];
            a[0] = t0.x; a[1] = t0.y; a[2] = t0.z; a[3] = t0.w;
            a[4] = t1.x; a[5] = t1.y; a[6] = t1.z; a[7] = t1.w;
            b[0] = t2.x; b[1] = t2.y; b[2] = t2.z; b[3] = t2.w;
            b[4] = t3.x; b[5] = t3.y; b[6] = t3.z; b[7] = t3.w;
#pragma unroll
            for (int x = 0; x < 8; x++)
#pragma unroll
                for (int y = 0; y < 8; y++) acc[x][y] += a[x] * b[y];
        }
    }

#pragma unroll
    for (int x = 0; x < 8; x++) {
        int row = tr * 4 + (x & 3) + ((x >> 2) * 64);
        int m = m0 + row;
#pragma unroll
        for (int y = 0; y < 8; y++) {
            int col = tc * 4 + (y & 3) + ((y >> 2) * 64);
            int n = n0 + col;
            float v = acc[x][y] + bias[n];
            if (OUT_QKV) {
                int b = m >> 10, t = m & 1023;
                int h = n >> 6, d = n & 63;
                C[((size_t)(b * Hc + h) * Tc + t) * Dc + d] = v;
            } else {
                C[(size_t)m * Ec + n] = v;
            }
        }
    }
}

// ---------------------------------------------------------------------------
// Kernel 3: fused attention (flash-style), one block per (64 q-rows, b*h)
// Smem: Qs 64x64, Ks 64x64 (XOR-swizzled for K, reused unswizzled for P), Vs
// 64x64 -> exactly 48 KB static. Thread (i=tid/16, j=tid%16) owns rows
// {i+16a}, cols {j+16b} of the 64x64 S tile and of the 64x64 O tile.
// ---------------------------------------------------------------------------
__global__ __launch_bounds__(256) void attn_kernel() {
    __shared__ float Qs[64 * 64];
    __shared__ float Ks[64 * 64];  // K (swizzled), then P (unswizzled)
    __shared__ float Vs[64 * 64];

    const int tid = threadIdx.x;
    const int i = tid >> 4;   // 0..15
    const int j = tid & 15;   // 0..15
    const int bh = blockIdx.y;
    const int q0 = blockIdx.x * 64;
    const int h = bh & (Hc - 1);

    const float* qbase = g_q + ((size_t)bh * Tc + q0) * Dc;
    const float* biasr = g_bias + h * NREL;
    const float scale = 0.125f;  // 1/sqrt(64)

    // load Q tile
    {
        int r = tid >> 2;
        int c0 = (tid & 3) * 16;
#pragma unroll
        for (int c = 0; c < 16; c += 4)
            *(float4*)&Qs[r * 64 + c0 + c] =
                *(const float4*)&qbase[r * 64 + c0 + c];
    }

    float m_[4], l_[4], O[4][4];
#pragma unroll
    for (int a = 0; a < 4; a++) {
        m_[a] = -1e30f;
        l_[a] = 0.0f;
#pragma unroll
        for (int b = 0; b < 4; b++) O[a][b] = 0.0f;
    }

    for (int kt = 0; kt < Tc / 64; kt++) {
        __syncthreads();  // prior phase B done with Ks/Vs
        // load K (swizzled along e) and V tiles
        {
            int r = tid >> 2;
            int c0 = (tid & 3) * 16;
            const float* kb = g_k + ((size_t)bh * Tc + kt * 64) * Dc;
            const float* vb = g_v + ((size_t)bh * Tc + kt * 64) * Dc;
#pragma unroll
            for (int c = 0; c < 16; c += 4) {
                int e = c0 + c;
                int esw = (((e >> 2) ^ (r & 7)) << 2);
                *(float4*)&Ks[r * 64 + esw] = *(const float4*)&kb[r * 64 + e];
                *(float4*)&Vs[r * 64 + e] = *(const float4*)&vb[r * 64 + e];
            }
        }
        __syncthreads();

        // phase A: S = Q K^T
        float s[4][4];
#pragma unroll
        for (int a = 0; a < 4; a++)
#pragma unroll
            for (int b = 0; b < 4; b++) s[a][b] = 0.0f;

#pragma unroll
        for (int e4 = 0; e4 < 16; e4++) {
            float4 qv[4], kv[4];
#pragma unroll
            for (int a = 0; a < 4; a++)
                qv[a] = *(const float4*)&Qs[(i + 16 * a) * 64 + e4 * 4];
#pragma unroll
            for (int b = 0; b < 4; b++) {
                int r = j + 16 * b;
                kv[b] = *(const float4*)&Ks[r * 64 + ((e4 ^ (r & 7)) << 2)];
            }
#pragma unroll
            for (int a = 0; a < 4; a++)
#pragma unroll
                for (int b = 0; b < 4; b++) {
                    s[a][b] += qv[a].x * kv[b].x;
                    s[a][b] += qv[a].y * kv[b].y;
                    s[a][b] += qv[a].z * kv[b].z;
                    s[a][b] += qv[a].w * kv[b].w;
                }
        }

        // scale + bias
#pragma unroll
        for (int a = 0; a < 4; a++)
#pragma unroll
            for (int b = 0; b < 4; b++) {
                int rel = (q0 + i + 16 * a) - (kt * 64 + j + 16 * b) + (Tc - 1);
                s[a][b] = s[a][b] * scale + __ldg(&biasr[rel]);
            }

        // online softmax (row reduce across the 16 j-lanes, same warp half)
#pragma unroll
        for (int a = 0; a < 4; a++) {
            float mx = fmaxf(fmaxf(s[a][0], s[a][1]), fmaxf(s[a][2], s[a][3]));
#pragma unroll
            for (int msk = 1; msk < 16; msk <<= 1)
                mx = fmaxf(mx, __shfl_xor_sync(0xffffffffu, mx, msk));
            float mn = fmaxf(m_[a], mx);
            float corr = __expf(m_[a] - mn);
            float sum = 0.0f;
#pragma unroll
            for (int b = 0; b < 4; b++) {
                s[a][b] = __expf(s[a][b] - mn);
                sum += s[a][b];
            }
#pragma unroll
            for (int msk = 1; msk < 16; msk <<= 1)
                sum += __shfl_xor_sync(0xffffffffu, sum, msk);
            l_[a] = l_[a] * corr + sum;
            m_[a] = mn;
#pragma unroll
            for (int b = 0; b < 4; b++) O[a][b] *= corr;
        }

        __syncthreads();  // all reads of Ks(K) done
        // write P into Ks (unswizzled)
#pragma unroll
        for (int a = 0; a < 4; a++)
#pragma unroll
            for (int b = 0; b < 4; b++)
                Ks[(i + 16 * a) * 64 + j + 16 * b] = s[a][b];
        __syncthreads();

        // phase B: O += P V
#pragma unroll
        for (int k4 = 0; k4 < 16; k4++) {
            float pv[4][4];
#pragma unroll
            for (int a = 0; a < 4; a++) {
                float4 t = *(const float4*)&Ks[(i + 16 * a) * 64 + k4 * 4];
                pv[a][0] = t.x; pv[a][1] = t.y; pv[a][2] = t.z; pv[a][3] = t.w;
            }
#pragma unroll
            for (int kk = 0; kk < 4; kk++) {
                float vb_[4];
#pragma unroll
                for (int b = 0; b < 4; b++)
                    vb_[b] = Vs[(k4 * 4 + kk) * 64 + j + 16 * b];
#pragma unroll
                for (int a = 0; a < 4; a++) {
                    float p = pv[a][kk];
#pragma unroll
                    for (int b = 0; b < 4; b++) O[a][b] += p * vb_[b];
                }
            }
        }
    }

    // normalize + store
    float* obase = g_ao + ((size_t)bh * Tc + q0) * Dc;
#pragma unroll
    for (int a = 0; a < 4; a++) {
        float inv = 1.0f / l_[a];
#pragma unroll
        for (int b = 0; b < 4; b++)
            obase[(i + 16 * a) * 64 + j + 16 * b] = O[a][b] * inv;
    }
}

// ---------------------------------------------------------------------------
extern "C" void kernel_launch(void* const* d_in, const int* in_sizes, int n_in,
                              void* d_out, int out_size) {
    (void)in_sizes; (void)n_in; (void)out_size;
    const float* query = (const float*)d_in[0];
    const float* key_ = (const float*)d_in[1];
    const float* value = (const float*)d_in[2];
    const float* Wq = (const float*)d_in[3];
    const float* bq = (const float*)d_in[4];
    const float* Wk = (const float*)d_in[5];
    const float* bk = (const float*)d_in[6];
    const float* Wv = (const float*)d_in[7];
    const float* bv = (const float*)d_in[8];
    const float* Wo = (const float*)d_in[9];
    const float* bo = (const float*)d_in[10];
    const float* bias_table = (const float*)d_in[11];
    const float* offset = (const float*)d_in[12];
    float* out = (float*)d_out;

    bias_kernel<<<32, 256>>>(bias_table, offset);

    dim3 ggrid(Ec / 128, Mc / 128);  // (8, 64)
    gemm_nt<0, 1><<<ggrid, 256>>>(query, Wq, bq, nullptr, 0);
    gemm_nt<0, 1><<<ggrid, 256>>>(key_, Wk, bk, nullptr, 1);
    gemm_nt<0, 1><<<ggrid, 256>>>(value, Wv, bv, nullptr, 2);

    dim3 agrid(Tc / 64, Bc * Hc);  // (16, 128)
    attn_kernel<<<agrid, 256>>>();

    gemm_nt<1, 0><<<ggrid, 256>>>(nullptr, Wo, bo, out, 0);
}

// round 10
// speedup vs baseline: 2.5051x; 2.5051x over previous
#include <cuda_runtime.h>
#include <cstdint>
#include <math.h>

// Problem constants
#define Bc 8
#define Tc 1024
#define Ec 1024
#define Hc 16
#define Dc 64
#define Mc (Bc * Tc)          // 8192
#define NREL (2 * Tc - 1)     // 2047

// Scratch (static device globals; no cudaMalloc allowed)
__device__ float g_q[(size_t)Bc * Hc * Tc * Dc];   // [B,H,T,D]
__device__ float g_k[(size_t)Bc * Hc * Tc * Dc];
__device__ float g_v[(size_t)Bc * Hc * Tc * Dc];
__device__ float g_ao[(size_t)Bc * Hc * Tc * Dc];  // attention output [B,H,T,D]
__device__ float g_bias[Hc * NREL];                // bias_rel[h][r]

// ---------------------------------------------------------------------------
// tf32 helpers (baseline PTX — works at target sm_103, no 'a' features)
// ---------------------------------------------------------------------------
__device__ __forceinline__ uint32_t f2t(float x) {
    uint32_t r;
    asm("cvt.rna.tf32.f32 %0, %1;" : "=r"(r) : "f"(x));
    return r;
}
__device__ __forceinline__ float f2tf(float x) { return __uint_as_float(f2t(x)); }

__device__ __forceinline__ void mma8(float* c, uint32_t a0, uint32_t a1,
                                     uint32_t a2, uint32_t a3, uint32_t b0,
                                     uint32_t b1) {
    asm volatile(
        "mma.sync.aligned.m16n8k8.row.col.f32.tf32.tf32.f32 "
        "{%0,%1,%2,%3}, {%4,%5,%6,%7}, {%8,%9}, {%0,%1,%2,%3};"
        : "+f"(c[0]), "+f"(c[1]), "+f"(c[2]), "+f"(c[3])
        : "r"(a0), "r"(a1), "r"(a2), "r"(a3), "r"(b0), "r"(b1));
}

// ---------------------------------------------------------------------------
// Kernel 1: precompute interpolated relative bias per (h, rel)
// ---------------------------------------------------------------------------
__global__ void bias_kernel(const float* __restrict__ table,  // [2T-1, H]
                            const float* __restrict__ offset) {
    float bounded = tanhf(offset[0]) * 0.5f;
    for (int idx = blockIdx.x * blockDim.x + threadIdx.x; idx < Hc * NREL;
         idx += gridDim.x * blockDim.x) {
        int h = idx / NREL;
        int r = idx - h * NREL;
        float adj = (float)r + bounded;
        adj = fminf(fmaxf(adj, 0.0f), (float)(NREL - 1));
        int lo = (int)floorf(adj);
        int hi = (int)ceilf(adj);
        float w = adj - (float)lo;
        float lov = table[lo * Hc + h];
        float hiv = table[hi * Hc + h];
        g_bias[h * NREL + r] = lov * (1.0f - w) + hiv * w;
    }
}

// ---------------------------------------------------------------------------
// tf32 mma.sync GEMM: C[M,N] = A[M,K] * W[N,K]^T + bias[N]
// CTA 128x128, 8 warps (4m x 2n), warp tile 32x64, KC=32 double-buffered.
// Smem rows padded to stride 36 floats -> fragment LDS bank == lane (conflict
// free). Operands rounded to tf32 (cvt.rna) at STS time.
//   IN_HEADS : gather A from g_ao [B,H,T,D]
//   OUT_QKV  : scatter C into [B,H,T,D] (sel -> g_q/g_k/g_v)
// ---------------------------------------------------------------------------
#define KC 32
#define ASTR 36
#define STAGE_F 9216  // floats per stage: (128*36)*2

template <int IN_HEADS, int OUT_QKV>
__global__ __launch_bounds__(256) void gemm_tc(const float* __restrict__ A,
                                               const float* __restrict__ W,
                                               const float* __restrict__ bias,
                                               float* __restrict__ Cplain,
                                               int sel) {
    extern __shared__ float sm[];

    const int tid = threadIdx.x;
    const int m0 = blockIdx.y * 128;
    const int n0 = blockIdx.x * 128;
    const int wid = tid >> 5, lane = tid & 31;
    const int wm = wid & 3, wn = wid >> 2;
    const int q = lane & 3, g = lane >> 2;

    float acc[2][8][4];
#pragma unroll
    for (int f = 0; f < 2; f++)
#pragma unroll
        for (int j = 0; j < 8; j++)
#pragma unroll
            for (int v = 0; v < 4; v++) acc[f][j][v] = 0.0f;

    const int lr = tid >> 1;             // 0..127
    const int lc0 = (tid & 1) * 16;      // 0 or 16

    const float* Wrow = W + (size_t)(n0 + lr) * Ec + lc0;
    const float* Arow = IN_HEADS ? nullptr : A + (size_t)(m0 + lr) * Ec + lc0;

    float4 areg[4], wreg[4];
    auto ldg_chunk = [&](int kt) {
        const float* asrc;
        if (IN_HEADS) {
            int m = m0 + lr;
            int b = m >> 10, t = m & 1023;
            int e = kt * KC + lc0;
            int h = e >> 6, d = e & 63;
            asrc = g_ao + (((size_t)(b * Hc + h) * Tc + t) * Dc + d);
        } else {
            asrc = Arow + kt * KC;
        }
        const float* wsrc = Wrow + kt * KC;
#pragma unroll
        for (int i = 0; i < 4; i++) {
            areg[i] = *(const float4*)(asrc + 4 * i);
            wreg[i] = *(const float4*)(wsrc + 4 * i);
        }
    };
    auto sts_chunk = [&](int p) {
        float* As = sm + p * STAGE_F;
        float* Ws = As + 4608;
#pragma unroll
        for (int i = 0; i < 4; i++) {
            float4 a = areg[i], w = wreg[i];
            a.x = f2tf(a.x); a.y = f2tf(a.y); a.z = f2tf(a.z); a.w = f2tf(a.w);
            w.x = f2tf(w.x); w.y = f2tf(w.y); w.z = f2tf(w.z); w.w = f2tf(w.w);
            *(float4*)(As + lr * ASTR + lc0 + 4 * i) = a;
            *(float4*)(Ws + lr * ASTR + lc0 + 4 * i) = w;
        }
    };

    ldg_chunk(0);
    sts_chunk(0);
    __syncthreads();
    int p = 0;

    for (int kt = 0; kt < Ec / KC; kt++) {
        if (kt + 1 < Ec / KC) ldg_chunk(kt + 1);

        const float* As = sm + p * STAGE_F;
        const float* Ws = As + 4608;
#pragma unroll
        for (int ks = 0; ks < KC / 8; ks++) {
            uint32_t af[2][4];
#pragma unroll
            for (int f = 0; f < 2; f++) {
                const float* ap = As + (wm * 32 + f * 16 + g) * ASTR + ks * 8 + q;
                af[f][0] = __float_as_uint(ap[0]);
                af[f][1] = __float_as_uint(ap[8 * ASTR]);
                af[f][2] = __float_as_uint(ap[4]);
                af[f][3] = __float_as_uint(ap[8 * ASTR + 4]);
            }
#pragma unroll
            for (int j = 0; j < 8; j++) {
                const float* bp = Ws + (wn * 64 + j * 8 + g) * ASTR + ks * 8 + q;
                uint32_t b0 = __float_as_uint(bp[0]);
                uint32_t b1 = __float_as_uint(bp[4]);
                mma8(acc[0][j], af[0][0], af[0][1], af[0][2], af[0][3], b0, b1);
                mma8(acc[1][j], af[1][0], af[1][1], af[1][2], af[1][3], b0, b1);
            }
        }
        __syncthreads();
        if (kt + 1 < Ec / KC) sts_chunk(p ^ 1);
        __syncthreads();
        p ^= 1;
    }

    // Epilogue: value (f, j, rr, q-pair): row = wm*32 + f*16 + rr*8 + g,
    // col = wn*64 + j*8 + 2q + {0,1}
#pragma unroll
    for (int f = 0; f < 2; f++) {
#pragma unroll
        for (int rr = 0; rr < 2; rr++) {
            int m = m0 + wm * 32 + f * 16 + rr * 8 + g;
#pragma unroll
            for (int j = 0; j < 8; j++) {
                int cl = wn * 64 + j * 8 + 2 * q;  // 0..127 local col
                int n = n0 + cl;
                float2 v;
                v.x = acc[f][j][rr * 2 + 0] + __ldg(bias + n);
                v.y = acc[f][j][rr * 2 + 1] + __ldg(bias + n + 1);
                if (OUT_QKV) {
                    float* C = (sel == 0) ? g_q : ((sel == 1) ? g_k : g_v);
                    int b = m >> 10, t = m & 1023;
                    int h = n >> 6, d = n & 63;
                    *(float2*)(C + ((size_t)(b * Hc + h) * Tc + t) * Dc + d) = v;
                } else {
                    *(float2*)(Cplain + (size_t)m * Ec + n) = v;
                }
            }
        }
    }
}

// ---------------------------------------------------------------------------
// Fused attention on tf32 mma.sync. Block = 128 q-rows x (b,h); 8 warps, each
// owning 16 q-rows -> softmax is warp-local. K/V streamed in 64-key chunks;
// V staged transposed [d][key]; P converted C-frag -> A-frag via shuffles.
// Smem stride 68 floats -> fragment LDS bank == lane (conflict free).
// ---------------------------------------------------------------------------
__global__ __launch_bounds__(256) void attn_tc() {
    extern __shared__ float sm[];
    float* Qs = sm;                  // 128*68
    float* Ks = Qs + 128 * 68;       // 64*68
    float* Vt = Ks + 64 * 68;        // 64*68 (transposed: [d][key])
    float* bs = Vt + 64 * 68;        // 191 bias values

    const int tid = threadIdx.x, wid = tid >> 5, lane = tid & 31;
    const int q = lane & 3, g = lane >> 2;
    const int bh = blockIdx.y;
    const int q0 = blockIdx.x * 128;
    const int h = bh & (Hc - 1);

    const float* Qg = g_q + ((size_t)bh * Tc + q0) * Dc;
    const float* Kg = g_k + (size_t)bh * Tc * Dc;
    const float* Vg = g_v + (size_t)bh * Tc * Dc;
    const float scale = 0.125f;

    // stage Q tile (tf32-rounded)
    {
        int r = tid >> 1, c0 = (tid & 1) * 32;
#pragma unroll
        for (int i = 0; i < 8; i++) {
            float4 v = *(const float4*)(Qg + r * 64 + c0 + 4 * i);
            v.x = f2tf(v.x); v.y = f2tf(v.y); v.z = f2tf(v.z); v.w = f2tf(v.w);
            *(float4*)(Qs + r * 68 + c0 + 4 * i) = v;
        }
    }

    const int r0 = wid * 16 + g;  // this thread's first q-row (block-local)
    float m_[2] = {-1e30f, -1e30f}, l_[2] = {0.0f, 0.0f};
    float O[8][4];
#pragma unroll
    for (int j = 0; j < 8; j++)
#pragma unroll
        for (int v = 0; v < 4; v++) O[j][v] = 0.0f;

    for (int kt = 0; kt < Tc / 64; kt++) {
        __syncthreads();  // previous chunk's reads of Ks/Vt done
        // stage K chunk [64 key][64 d]
        {
            int key = tid >> 2, c0 = (tid & 3) * 16;
            const float* src = Kg + (size_t)(kt * 64 + key) * 64 + c0;
#pragma unroll
            for (int i = 0; i < 4; i++) {
                float4 v = *(const float4*)(src + 4 * i);
                v.x = f2tf(v.x); v.y = f2tf(v.y); v.z = f2tf(v.z); v.w = f2tf(v.w);
                *(float4*)(Ks + key * 68 + c0 + 4 * i) = v;
            }
        }
        // stage V chunk transposed -> Vt[d][key]
        {
            int key = tid & 63, d0 = (tid >> 6) * 16;
            const float* src = Vg + (size_t)(kt * 64 + key) * 64 + d0;
#pragma unroll
            for (int i = 0; i < 4; i++) {
                float4 v = *(const float4*)(src + 4 * i);
                Vt[(d0 + 4 * i + 0) * 68 + key] = f2tf(v.x);
                Vt[(d0 + 4 * i + 1) * 68 + key] = f2tf(v.y);
                Vt[(d0 + 4 * i + 2) * 68 + key] = f2tf(v.z);
                Vt[(d0 + 4 * i + 3) * 68 + key] = f2tf(v.w);
            }
        }
        if (tid < 191)
            bs[tid] = g_bias[h * NREL + q0 - kt * 64 + 960 + tid];
        __syncthreads();

        // phase A: S = Q K^T (warp tile 16 x 64)
        float s[8][4];
#pragma unroll
        for (int j = 0; j < 8; j++)
#pragma unroll
            for (int v = 0; v < 4; v++) s[j][v] = 0.0f;
#pragma unroll
        for (int ks = 0; ks < 8; ks++) {
            const float* ap = Qs + (wid * 16 + g) * 68 + ks * 8 + q;
            uint32_t a0 = __float_as_uint(ap[0]);
            uint32_t a1 = __float_as_uint(ap[8 * 68]);
            uint32_t a2 = __float_as_uint(ap[4]);
            uint32_t a3 = __float_as_uint(ap[8 * 68 + 4]);
#pragma unroll
            for (int j = 0; j < 8; j++) {
                const float* bp = Ks + (j * 8 + g) * 68 + ks * 8 + q;
                mma8(s[j], a0, a1, a2, a3, __float_as_uint(bp[0]),
                     __float_as_uint(bp[4]));
            }
        }

        // scale + bias, row maxima
        float mx0 = -1e30f, mx1 = -1e30f;
#pragma unroll
        for (int j = 0; j < 8; j++) {
            int c = j * 8 + 2 * q;  // key within chunk
            s[j][0] = s[j][0] * scale + bs[r0 - c + 63];
            s[j][1] = s[j][1] * scale + bs[r0 - c + 62];
            s[j][2] = s[j][2] * scale + bs[r0 - c + 71];
            s[j][3] = s[j][3] * scale + bs[r0 - c + 70];
            mx0 = fmaxf(mx0, fmaxf(s[j][0], s[j][1]));
            mx1 = fmaxf(mx1, fmaxf(s[j][2], s[j][3]));
        }
        mx0 = fmaxf(mx0, __shfl_xor_sync(0xffffffffu, mx0, 1));
        mx0 = fmaxf(mx0, __shfl_xor_sync(0xffffffffu, mx0, 2));
        mx1 = fmaxf(mx1, __shfl_xor_sync(0xffffffffu, mx1, 1));
        mx1 = fmaxf(mx1, __shfl_xor_sync(0xffffffffu, mx1, 2));

        float mn0 = fmaxf(m_[0], mx0), mn1 = fmaxf(m_[1], mx1);
        float corr0 = __expf(m_[0] - mn0), corr1 = __expf(m_[1] - mn1);
        float sum0 = 0.0f, sum1 = 0.0f;
#pragma unroll
        for (int j = 0; j < 8; j++) {
            s[j][0] = __expf(s[j][0] - mn0);
            s[j][1] = __expf(s[j][1] - mn0);
            s[j][2] = __expf(s[j][2] - mn1);
            s[j][3] = __expf(s[j][3] - mn1);
            sum0 += s[j][0] + s[j][1];
            sum1 += s[j][2] + s[j][3];
        }
        sum0 += __shfl_xor_sync(0xffffffffu, sum0, 1);
        sum0 += __shfl_xor_sync(0xffffffffu, sum0, 2);
        sum1 += __shfl_xor_sync(0xffffffffu, sum1, 1);
        sum1 += __shfl_xor_sync(0xffffffffu, sum1, 2);
        l_[0] = l_[0] * corr0 + sum0;
        l_[1] = l_[1] * corr1 + sum1;
        m_[0] = mn0;
        m_[1] = mn1;
#pragma unroll
        for (int j = 0; j < 8; j++) {
            O[j][0] *= corr0; O[j][1] *= corr0;
            O[j][2] *= corr1; O[j][3] *= corr1;
        }

        // phase B: O += P V. Convert P C-frag -> A-frag via shuffles per k-step.
        const int base = lane & ~3;
        const int s0l = base + (q >> 1);
        const int s1l = base + 2 + (q >> 1);
        const bool odd = (q & 1);
#pragma unroll
        for (int j = 0; j < 8; j++) {
            float t00 = __shfl_sync(0xffffffffu, s[j][0], s0l);
            float t01 = __shfl_sync(0xffffffffu, s[j][1], s0l);
            float t10 = __shfl_sync(0xffffffffu, s[j][0], s1l);
            float t11 = __shfl_sync(0xffffffffu, s[j][1], s1l);
            float t20 = __shfl_sync(0xffffffffu, s[j][2], s0l);
            float t21 = __shfl_sync(0xffffffffu, s[j][3], s0l);
            float t30 = __shfl_sync(0xffffffffu, s[j][2], s1l);
            float t31 = __shfl_sync(0xffffffffu, s[j][3], s1l);
            uint32_t a0 = f2t(odd ? t01 : t00);  // (row g,   key q)
            uint32_t a1 = f2t(odd ? t21 : t20);  // (row g+8, key q)
            uint32_t a2 = f2t(odd ? t11 : t10);  // (row g,   key q+4)
            uint32_t a3 = f2t(odd ? t31 : t30);  // (row g+8, key q+4)
#pragma unroll
            for (int n = 0; n < 8; n++) {
                const float* bp = Vt + (n * 8 + g) * 68 + j * 8 + q;
                mma8(O[n], a0, a1, a2, a3, __float_as_uint(bp[0]),
                     __float_as_uint(bp[4]));
            }
        }
    }

    // normalize + store [B,H,T,D]
    float inv0 = 1.0f / l_[0], inv1 = 1.0f / l_[1];
    float* Og = g_ao + ((size_t)bh * Tc + q0 + wid * 16) * Dc;
#pragma unroll
    for (int j = 0; j < 8; j++) {
        int d = j * 8 + 2 * q;
        float2 v0 = {O[j][0] * inv0, O[j][1] * inv0};
        float2 v1 = {O[j][2] * inv1, O[j][3] * inv1};
        *(float2*)(Og + g * 64 + d) = v0;
        *(float2*)(Og + (g + 8) * 64 + d) = v1;
    }
}

// ---------------------------------------------------------------------------
extern "C" void kernel_launch(void* const* d_in, const int* in_sizes, int n_in,
                              void* d_out, int out_size) {
    (void)in_sizes; (void)n_in; (void)out_size;
    const float* query = (const float*)d_in[0];
    const float* key_ = (const float*)d_in[1];
    const float* value = (const float*)d_in[2];
    const float* Wq = (const float*)d_in[3];
    const float* bq = (const float*)d_in[4];
    const float* Wk = (const float*)d_in[5];
    const float* bk = (const float*)d_in[6];
    const float* Wv = (const float*)d_in[7];
    const float* bv = (const float*)d_in[8];
    const float* Wo = (const float*)d_in[9];
    const float* bo = (const float*)d_in[10];
    const float* bias_table = (const float*)d_in[11];
    const float* offset = (const float*)d_in[12];
    float* out = (float*)d_out;

    const int SMEM_GEMM = 2 * STAGE_F * 4;             // 73728 B
    const int SMEM_ATTN = (128 * 68 + 2 * 64 * 68 + 192) * 4;  // 70400 B
    cudaFuncSetAttribute(gemm_tc<0, 1>,
                         cudaFuncAttributeMaxDynamicSharedMemorySize, SMEM_GEMM);
    cudaFuncSetAttribute(gemm_tc<1, 0>,
                         cudaFuncAttributeMaxDynamicSharedMemorySize, SMEM_GEMM);
    cudaFuncSetAttribute(attn_tc, cudaFuncAttributeMaxDynamicSharedMemorySize,
                         SMEM_ATTN);

    bias_kernel<<<32, 256>>>(bias_table, offset);

    dim3 ggrid(Ec / 128, Mc / 128);  // (8, 64)
    gemm_tc<0, 1><<<ggrid, 256, SMEM_GEMM>>>(query, Wq, bq, nullptr, 0);
    gemm_tc<0, 1><<<ggrid, 256, SMEM_GEMM>>>(key_, Wk, bk, nullptr, 1);
    gemm_tc<0, 1><<<ggrid, 256, SMEM_GEMM>>>(value, Wv, bv, nullptr, 2);

    dim3 agrid(Tc / 128, Bc * Hc);  // (8, 128)
    attn_tc<<<agrid, 256, SMEM_ATTN>>>();

    gemm_tc<1, 0><<<ggrid, 256, SMEM_GEMM>>>(nullptr, Wo, bo, out, 0);
}

// round 11
// speedup vs baseline: 2.6938x; 1.0753x over previous
#include <cuda_runtime.h>
#include <cstdint>
#include <math.h>

// Problem constants
#define Bc 8
#define Tc 1024
#define Ec 1024
#define Hc 16
#define Dc 64
#define Mc (Bc * Tc)          // 8192
#define NREL (2 * Tc - 1)     // 2047

// Scratch (static device globals; no cudaMalloc allowed)
__device__ float g_q[(size_t)Bc * Hc * Tc * Dc];   // [B,H,T,D] (tf32-rounded)
__device__ float g_k[(size_t)Bc * Hc * Tc * Dc];
__device__ float g_v[(size_t)Bc * Hc * Tc * Dc];
__device__ float g_ao[(size_t)Bc * Hc * Tc * Dc];  // attn out, rounded + k-permuted
__device__ float g_bias[Hc * NREL];                // bias_rel[h][r]
__device__ float g_ar[(size_t)3 * Mc * Ec];        // rounded+permuted A (q,k,v)
__device__ float g_wr[(size_t)4 * Ec * Ec];        // rounded+permuted W (q,k,v,o)

// ---------------------------------------------------------------------------
// tf32 + cp.async helpers (baseline PTX — compiles at target sm_103)
// ---------------------------------------------------------------------------
__device__ __forceinline__ uint32_t f2t(float x) {
    uint32_t r;
    asm("cvt.rna.tf32.f32 %0, %1;" : "=r"(r) : "f"(x));
    return r;
}
__device__ __forceinline__ float f2tf(float x) { return __uint_as_float(f2t(x)); }

__device__ __forceinline__ void mma8(float* c, uint32_t a0, uint32_t a1,
                                     uint32_t a2, uint32_t a3, uint32_t b0,
                                     uint32_t b1) {
    asm volatile(
        "mma.sync.aligned.m16n8k8.row.col.f32.tf32.tf32.f32 "
        "{%0,%1,%2,%3}, {%4,%5,%6,%7}, {%8,%9}, {%0,%1,%2,%3};"
        : "+f"(c[0]), "+f"(c[1]), "+f"(c[2]), "+f"(c[3])
        : "r"(a0), "r"(a1), "r"(a2), "r"(a3), "r"(b0), "r"(b1));
}

__device__ __forceinline__ uint32_t smem_to_u32(const void* p) {
    uint32_t a;
    asm("{ .reg .u64 t; cvta.to.shared.u64 t, %1; cvt.u32.u64 %0, t; }"
        : "=r"(a) : "l"(p));
    return a;
}
__device__ __forceinline__ void cp16(uint32_t dst, const float* src) {
    asm volatile("cp.async.cg.shared.global [%0], [%1], 16;"
                 :: "r"(dst), "l"(src));
}
#define CP_COMMIT() asm volatile("cp.async.commit_group;" ::: "memory")
#define CP_WAIT0() asm volatile("cp.async.wait_group 0;" ::: "memory")

// ---------------------------------------------------------------------------
// Kernel: precompute interpolated relative bias per (h, rel)
// ---------------------------------------------------------------------------
__global__ void bias_kernel(const float* __restrict__ table,  // [2T-1, H]
                            const float* __restrict__ offset) {
    float bounded = tanhf(offset[0]) * 0.5f;
    for (int idx = blockIdx.x * blockDim.x + threadIdx.x; idx < Hc * NREL;
         idx += gridDim.x * blockDim.x) {
        int h = idx / NREL;
        int r = idx - h * NREL;
        float adj = (float)r + bounded;
        adj = fminf(fmaxf(adj, 0.0f), (float)(NREL - 1));
        int lo = (int)floorf(adj);
        int hi = (int)ceilf(adj);
        float w = adj - (float)lo;
        float lov = table[lo * Hc + h];
        float hiv = table[hi * Hc + h];
        g_bias[h * NREL + r] = lov * (1.0f - w) + hiv * w;
    }
}

// ---------------------------------------------------------------------------
// Conversion: tf32-round + k-permute (within each 8-group: dst[2(k&3)+(k>>2)])
// Fragment elements (q, q+4) become adjacent -> LDS.64 fragment loads.
// ---------------------------------------------------------------------------
__global__ void conv_perm3(const float* __restrict__ s0,
                           const float* __restrict__ s1,
                           const float* __restrict__ s2) {
    const int n8 = Mc * Ec / 8;
    for (int idx = blockIdx.x * blockDim.x + threadIdx.x; idx < 3 * n8;
         idx += gridDim.x * blockDim.x) {
        int a = idx / n8, r = idx - a * n8;
        const float* s = (a == 0) ? s0 : ((a == 1) ? s1 : s2);
        float4 x = ((const float4*)s)[2 * r];
        float4 y = ((const float4*)s)[2 * r + 1];
        float4 o0 = {f2tf(x.x), f2tf(y.x), f2tf(x.y), f2tf(y.y)};
        float4 o1 = {f2tf(x.z), f2tf(y.z), f2tf(x.w), f2tf(y.w)};
        float4* d = (float4*)(g_ar + (size_t)a * (Mc * Ec) + (size_t)r * 8);
        d[0] = o0;
        d[1] = o1;
    }
}

__global__ void conv_perm4(const float* __restrict__ s0,
                           const float* __restrict__ s1,
                           const float* __restrict__ s2,
                           const float* __restrict__ s3) {
    const int n8 = Ec * Ec / 8;
    for (int idx = blockIdx.x * blockDim.x + threadIdx.x; idx < 4 * n8;
         idx += gridDim.x * blockDim.x) {
        int a = idx / n8, r = idx - a * n8;
        const float* s = (a == 0) ? s0 : ((a == 1) ? s1 : ((a == 2) ? s2 : s3));
        float4 x = ((const float4*)s)[2 * r];
        float4 y = ((const float4*)s)[2 * r + 1];
        float4 o0 = {f2tf(x.x), f2tf(y.x), f2tf(x.y), f2tf(y.y)};
        float4 o1 = {f2tf(x.z), f2tf(y.z), f2tf(x.w), f2tf(y.w)};
        float4* d = (float4*)(g_wr + (size_t)a * (Ec * Ec) + (size_t)r * 8);
        d[0] = o0;
        d[1] = o1;
    }
}

// ---------------------------------------------------------------------------
// tf32 mma.sync GEMM v2: cp.async double-buffered, 1 sync/chunk, LDS.64 frags.
// C[M,N] = A[M,K] * W[N,K]^T + bias[N].  CTA 128x128, 8 warps (4m x 2n).
// Operands pre-rounded + k-permuted.  OUT_QKV: z = blockIdx.z selects
// (A slice, W slice, bias, dst g_q/g_k/g_v); epilogue rounds for attention.
// IN_HEADS: A gathered from g_ao (already rounded+permuted by attention).
// ---------------------------------------------------------------------------
#define KC 32
#define ASTR 40
#define STG_F (128 * ASTR)       // 5120 floats per operand per stage
#define STAGE_F (2 * STG_F)      // 10240 floats per stage (A + W)
#define SMEM_GEMM (2 * STAGE_F * 4)  // 81920 B

template <int IN_HEADS, int OUT_QKV>
__global__ __launch_bounds__(256, 2) void gemm_tc(
    const float* __restrict__ bias0, const float* __restrict__ bias1,
    const float* __restrict__ bias2, float* __restrict__ Cplain) {
    extern __shared__ float sm[];
    const uint32_t smb = smem_to_u32(sm);

    const int tid = threadIdx.x;
    const int m0 = blockIdx.y * 128;
    const int n0 = blockIdx.x * 128;
    const int z = OUT_QKV ? blockIdx.z : 3;  // W slot 3 = Wo
    const int wid = tid >> 5, lane = tid & 31;
    const int wm = wid & 3, wn = wid >> 2;
    const int q = lane & 3, g = lane >> 2;

    const float* bias =
        OUT_QKV ? (z == 0 ? bias0 : (z == 1 ? bias1 : bias2)) : bias0;

    const int lr = tid >> 1, lc0 = (tid & 1) * 16;
    const float* Wrow = g_wr + (size_t)z * (Ec * Ec) + (size_t)(n0 + lr) * Ec + lc0;
    const float* Arow =
        IN_HEADS ? nullptr
                 : g_ar + (size_t)z * (Mc * Ec) + (size_t)(m0 + lr) * Ec + lc0;

    auto fill = [&](int kt, int p) {
        uint32_t dA = smb + (uint32_t)(p * STAGE_F + lr * ASTR + lc0) * 4u;
        uint32_t dW = dA + STG_F * 4u;
        const float* sA;
        if (IN_HEADS) {
            int m = m0 + lr, bb = m >> 10, t = m & 1023;
            int e = kt * KC + lc0, h = e >> 6, d = e & 63;
            sA = g_ao + (((size_t)(bb * Hc + h) * Tc + t) * Dc + d);
        } else {
            sA = Arow + kt * KC;
        }
        const float* sW = Wrow + kt * KC;
#pragma unroll
        for (int i = 0; i < 4; i++) {
            cp16(dA + 16u * i, sA + 4 * i);
            cp16(dW + 16u * i, sW + 4 * i);
        }
    };

    float acc[2][8][4];
#pragma unroll
    for (int f = 0; f < 2; f++)
#pragma unroll
        for (int j = 0; j < 8; j++)
#pragma unroll
            for (int v = 0; v < 4; v++) acc[f][j][v] = 0.0f;

    fill(0, 0);
    CP_COMMIT();

    for (int kt = 0; kt < Ec / KC; kt++) {
        const int p = kt & 1;
        CP_WAIT0();
        __syncthreads();
        if (kt + 1 < Ec / KC) fill(kt + 1, p ^ 1);
        CP_COMMIT();

        const float* As = sm + p * STAGE_F;
        const float* Ws = As + STG_F;
#pragma unroll
        for (int ks = 0; ks < 4; ks++) {
            uint32_t af[2][4];
#pragma unroll
            for (int f = 0; f < 2; f++) {
                const float* ap =
                    As + (wm * 32 + f * 16 + g) * ASTR + ks * 8 + 2 * q;
                float2 lo = *(const float2*)ap;
                float2 hi = *(const float2*)(ap + 8 * ASTR);
                af[f][0] = __float_as_uint(lo.x);  // A[g][q]
                af[f][1] = __float_as_uint(hi.x);  // A[g+8][q]
                af[f][2] = __float_as_uint(lo.y);  // A[g][q+4]
                af[f][3] = __float_as_uint(hi.y);  // A[g+8][q+4]
            }
#pragma unroll
            for (int j = 0; j < 8; j++) {
                const float* bp =
                    Ws + (wn * 64 + j * 8 + g) * ASTR + ks * 8 + 2 * q;
                float2 bf = *(const float2*)bp;
                uint32_t b0 = __float_as_uint(bf.x);
                uint32_t b1 = __float_as_uint(bf.y);
                mma8(acc[0][j], af[0][0], af[0][1], af[0][2], af[0][3], b0, b1);
                mma8(acc[1][j], af[1][0], af[1][1], af[1][2], af[1][3], b0, b1);
            }
        }
    }

    // Epilogue: row = wm*32 + f*16 + rr*8 + g, col = wn*64 + j*8 + 2q + {0,1}
#pragma unroll
    for (int f = 0; f < 2; f++) {
#pragma unroll
        for (int rr = 0; rr < 2; rr++) {
            int m = m0 + wm * 32 + f * 16 + rr * 8 + g;
#pragma unroll
            for (int j = 0; j < 8; j++) {
                int n = n0 + wn * 64 + j * 8 + 2 * q;
                float vx = acc[f][j][rr * 2 + 0] + __ldg(bias + n);
                float vy = acc[f][j][rr * 2 + 1] + __ldg(bias + n + 1);
                if (OUT_QKV) {
                    float* C = (z == 0) ? g_q : ((z == 1) ? g_k : g_v);
                    int bb = m >> 10, t = m & 1023;
                    int h = n >> 6, d = n & 63;
                    float2 v = {f2tf(vx), f2tf(vy)};  // pre-round for attention
                    *(float2*)(C + ((size_t)(bb * Hc + h) * Tc + t) * Dc + d) = v;
                } else {
                    float2 v = {vx, vy};
                    *(float2*)(Cplain + (size_t)m * Ec + n) = v;
                }
            }
        }
    }
}

// ---------------------------------------------------------------------------
// Fused attention v2: cp.async double-buffered K/V, one sync per chunk,
// bias window staged once.  Block = 128 q-rows x (b,h); 8 warps; softmax
// warp-local.  Qs/Ks stride 68 (conflict-free frags), Vs stride 72 row-major
// (conflict-free as B operand: banks 8q+g).  Output stored rounded+permuted
// into g_ao for the final GEMM.
// ---------------------------------------------------------------------------
#define OQ 0
#define OK0 (128 * 68)          // 8704
#define OK1 (OK0 + 64 * 68)     // 13056
#define OV0 (OK1 + 64 * 68)     // 17408
#define OV1 (OV0 + 64 * 72)     // 22016
#define OSB (OV1 + 64 * 72)     // 26624
#define SMEM_ATTN ((OSB + 1152) * 4)  // 111104 B

__global__ __launch_bounds__(256, 2) void attn_tc() {
    extern __shared__ float sm[];
    const uint32_t smb = smem_to_u32(sm);
    float* sb = sm + OSB;

    const int tid = threadIdx.x, wid = tid >> 5, lane = tid & 31;
    const int q = lane & 3, g = lane >> 2;
    const int bh = blockIdx.y;
    const int q0 = blockIdx.x * 128;
    const int h = bh & (Hc - 1);

    const float* Qg = g_q + ((size_t)bh * Tc + q0) * Dc;
    const float* Kg = g_k + (size_t)bh * Tc * Dc;
    const float* Vg = g_v + (size_t)bh * Tc * Dc;
    const float scale = 0.125f;

    auto fillKV = [&](int kt, int p) {
        int krow = tid >> 2, c = (tid & 3) * 16;
        uint32_t dK = smb + (uint32_t)((p ? OK1 : OK0) + krow * 68 + c) * 4u;
        uint32_t dV = smb + (uint32_t)((p ? OV1 : OV0) + krow * 72 + c) * 4u;
        const float* sK = Kg + (size_t)(kt * 64 + krow) * 64 + c;
        const float* sV = Vg + (size_t)(kt * 64 + krow) * 64 + c;
#pragma unroll
        for (int i = 0; i < 4; i++) {
            cp16(dK + 16u * i, sK + 4 * i);
            cp16(dV + 16u * i, sV + 4 * i);
        }
    };

    // prologue: Q + KV chunk 0 (one group), bias window
    {
        int r = tid >> 1, c0 = (tid & 1) * 32;
        uint32_t dQ = smb + (uint32_t)(OQ + r * 68 + c0) * 4u;
        const float* sQ = Qg + r * 64 + c0;
#pragma unroll
        for (int i = 0; i < 8; i++) cp16(dQ + 16u * i, sQ + 4 * i);
    }
    fillKV(0, 0);
    CP_COMMIT();
    for (int i = tid; i < 1151; i += 256) sb[i] = g_bias[h * NREL + q0 + i];

    const int r0 = wid * 16 + g;  // block-local first q-row of this thread
    float m_[2] = {-1e30f, -1e30f}, l_[2] = {0.0f, 0.0f};
    float O[8][4];
#pragma unroll
    for (int j = 0; j < 8; j++)
#pragma unroll
        for (int v = 0; v < 4; v++) O[j][v] = 0.0f;

    for (int kt = 0; kt < Tc / 64; kt++) {
        const int p = kt & 1;
        CP_WAIT0();
        __syncthreads();
        if (kt + 1 < Tc / 64) fillKV(kt + 1, p ^ 1);
        CP_COMMIT();

        const float* Ks = sm + (p ? OK1 : OK0);
        const float* Vs = sm + (p ? OV1 : OV0);

        // phase A: S = Q K^T (warp tile 16 x 64)
        float s[8][4];
#pragma unroll
        for (int j = 0; j < 8; j++)
#pragma unroll
            for (int v = 0; v < 4; v++) s[j][v] = 0.0f;
#pragma unroll
        for (int ks = 0; ks < 8; ks++) {
            const float* ap = sm + OQ + (wid * 16 + g) * 68 + ks * 8 + q;
            uint32_t a0 = __float_as_uint(ap[0]);
            uint32_t a1 = __float_as_uint(ap[8 * 68]);
            uint32_t a2 = __float_as_uint(ap[4]);
            uint32_t a3 = __float_as_uint(ap[8 * 68 + 4]);
#pragma unroll
            for (int j = 0; j < 8; j++) {
                const float* bp = Ks + (j * 8 + g) * 68 + ks * 8 + q;
                mma8(s[j], a0, a1, a2, a3, __float_as_uint(bp[0]),
                     __float_as_uint(bp[4]));
            }
        }

        // scale + bias, row maxima
        float mx0 = -1e30f, mx1 = -1e30f;
#pragma unroll
        for (int j = 0; j < 8; j++) {
            int i0 = r0 - kt * 64 - (j * 8 + 2 * q) + 1023;
            s[j][0] = s[j][0] * scale + sb[i0];
            s[j][1] = s[j][1] * scale + sb[i0 - 1];
            s[j][2] = s[j][2] * scale + sb[i0 + 8];
            s[j][3] = s[j][3] * scale + sb[i0 + 7];
            mx0 = fmaxf(mx0, fmaxf(s[j][0], s[j][1]));
            mx1 = fmaxf(mx1, fmaxf(s[j][2], s[j][3]));
        }
        mx0 = fmaxf(mx0, __shfl_xor_sync(0xffffffffu, mx0, 1));
        mx0 = fmaxf(mx0, __shfl_xor_sync(0xffffffffu, mx0, 2));
        mx1 = fmaxf(mx1, __shfl_xor_sync(0xffffffffu, mx1, 1));
        mx1 = fmaxf(mx1, __shfl_xor_sync(0xffffffffu, mx1, 2));

        float mn0 = fmaxf(m_[0], mx0), mn1 = fmaxf(m_[1], mx1);
        float corr0 = __expf(m_[0] - mn0), corr1 = __expf(m_[1] - mn1);
        float sum0 = 0.0f, sum1 = 0.0f;
#pragma unroll
        for (int j = 0; j < 8; j++) {
            s[j][0] = __expf(s[j][0] - mn0);
            s[j][1] = __expf(s[j][1] - mn0);
            s[j][2] = __expf(s[j][2] - mn1);
            s[j][3] = __expf(s[j][3] - mn1);
            sum0 += s[j][0] + s[j][1];
            sum1 += s[j][2] + s[j][3];
        }
        sum0 += __shfl_xor_sync(0xffffffffu, sum0, 1);
        sum0 += __shfl_xor_sync(0xffffffffu, sum0, 2);
        sum1 += __shfl_xor_sync(0xffffffffu, sum1, 1);
        sum1 += __shfl_xor_sync(0xffffffffu, sum1, 2);
        l_[0] = l_[0] * corr0 + sum0;
        l_[1] = l_[1] * corr1 + sum1;
        m_[0] = mn0;
        m_[1] = mn1;
#pragma unroll
        for (int j = 0; j < 8; j++) {
            O[j][0] *= corr0; O[j][1] *= corr0;
            O[j][2] *= corr1; O[j][3] *= corr1;
        }

        // phase B: O += P V.  P C-frag -> A-frag via shuffles; V row-major
        // stride 72 as B operand (banks 8q+g, conflict-free).
        const int base = lane & ~3;
        const int s0l = base + (q >> 1);
        const int s1l = base + 2 + (q >> 1);
        const bool odd = (q & 1);
#pragma unroll
        for (int j = 0; j < 8; j++) {
            float t00 = __shfl_sync(0xffffffffu, s[j][0], s0l);
            float t01 = __shfl_sync(0xffffffffu, s[j][1], s0l);
            float t10 = __shfl_sync(0xffffffffu, s[j][0], s1l);
            float t11 = __shfl_sync(0xffffffffu, s[j][1], s1l);
            float t20 = __shfl_sync(0xffffffffu, s[j][2], s0l);
            float t21 = __shfl_sync(0xffffffffu, s[j][3], s0l);
            float t30 = __shfl_sync(0xffffffffu, s[j][2], s1l);
            float t31 = __shfl_sync(0xffffffffu, s[j][3], s1l);
            uint32_t a0 = f2t(odd ? t01 : t00);  // P(row g,   key j*8+q)
            uint32_t a1 = f2t(odd ? t21 : t20);  // P(row g+8, key j*8+q)
            uint32_t a2 = f2t(odd ? t11 : t10);  // P(row g,   key j*8+q+4)
            uint32_t a3 = f2t(odd ? t31 : t30);  // P(row g+8, key j*8+q+4)
#pragma unroll
            for (int n = 0; n < 8; n++) {
                const float* bp0 = Vs + (j * 8 + q) * 72 + n * 8 + g;
                const float* bp1 = Vs + (j * 8 + q + 4) * 72 + n * 8 + g;
                mma8(O[n], a0, a1, a2, a3, __float_as_uint(*bp0),
                     __float_as_uint(*bp1));
            }
        }
    }

    // normalize + store rounded & k-permuted into g_ao (for the Wo GEMM)
    float inv0 = 1.0f / l_[0], inv1 = 1.0f / l_[1];
    const int kk0 = 2 * q, kk1 = 2 * q + 1;
    const int p0 = 2 * (kk0 & 3) + (kk0 >> 2);
    const int p1 = 2 * (kk1 & 3) + (kk1 >> 2);
    float* Og = g_ao + ((size_t)bh * Tc + q0 + wid * 16) * Dc;
#pragma unroll
    for (int j = 0; j < 8; j++) {
        int cb = j * 8;
        Og[g * 64 + cb + p0] = f2tf(O[j][0] * inv0);
        Og[g * 64 + cb + p1] = f2tf(O[j][1] * inv0);
        Og[(g + 8) * 64 + cb + p0] = f2tf(O[j][2] * inv1);
        Og[(g + 8) * 64 + cb + p1] = f2tf(O[j][3] * inv1);
    }
}

// ---------------------------------------------------------------------------
extern "C" void kernel_launch(void* const* d_in, const int* in_sizes, int n_in,
                              void* d_out, int out_size) {
    (void)in_sizes; (void)n_in; (void)out_size;
    const float* query = (const float*)d_in[0];
    const float* key_ = (const float*)d_in[1];
    const float* value = (const float*)d_in[2];
    const float* Wq = (const float*)d_in[3];
    const float* bq = (const float*)d_in[4];
    const float* Wk = (const float*)d_in[5];
    const float* bk = (const float*)d_in[6];
    const float* Wv = (const float*)d_in[7];
    const float* bv = (const float*)d_in[8];
    const float* Wo = (const float*)d_in[9];
    const float* bo = (const float*)d_in[10];
    const float* bias_table = (const float*)d_in[11];
    const float* offset = (const float*)d_in[12];
    float* out = (float*)d_out;

    cudaFuncSetAttribute(gemm_tc<0, 1>,
                         cudaFuncAttributeMaxDynamicSharedMemorySize, SMEM_GEMM);
    cudaFuncSetAttribute(gemm_tc<1, 0>,
                         cudaFuncAttributeMaxDynamicSharedMemorySize, SMEM_GEMM);
    cudaFuncSetAttribute(attn_tc, cudaFuncAttributeMaxDynamicSharedMemorySize,
                         SMEM_ATTN);

    bias_kernel<<<32, 256>>>(bias_table, offset);
    conv_perm3<<<4096, 256>>>(query, key_, value);
    conv_perm4<<<2048, 256>>>(Wq, Wk, Wv, Wo);

    dim3 ggrid(Ec / 128, Mc / 128, 3);  // QKV fused: (8, 64, 3)
    gemm_tc<0, 1><<<ggrid, 256, SMEM_GEMM>>>(bq, bk, bv, nullptr);

    dim3 agrid(Tc / 128, Bc * Hc);  // (8, 128)
    attn_tc<<<agrid, 256, SMEM_ATTN>>>();

    dim3 ogrid(Ec / 128, Mc / 128, 1);
    gemm_tc<1, 0><<<ogrid, 256, SMEM_GEMM>>>(bo, nullptr, nullptr, out);
}

// round 12
// speedup vs baseline: 2.9695x; 1.1023x over previous
#include <cuda_runtime.h>
#include <cstdint>
#include <math.h>

// Problem constants
#define Bc 8
#define Tc 1024
#define Ec 1024
#define Hc 16
#define Dc 64
#define Mc (Bc * Tc)          // 8192
#define NREL (2 * Tc - 1)     // 2047

// Scratch (static device globals; no cudaMalloc allowed)
__device__ float g_q[(size_t)Bc * Hc * Tc * Dc];   // [B,H,T,D] rounded, d-permuted
__device__ float g_k[(size_t)Bc * Hc * Tc * Dc];   // rounded, d-permuted
__device__ float g_v[(size_t)Bc * Hc * Tc * Dc];   // rounded, plain d
__device__ float g_ao[(size_t)Bc * Hc * Tc * Dc];  // attn out, rounded+permuted
__device__ float g_bias[Hc * NREL];                // bias_rel[h][r]
__device__ float g_ar[(size_t)3 * Mc * Ec];        // rounded+permuted A (q,k,v)
__device__ float g_wr[(size_t)4 * Ec * Ec];        // rounded+permuted W (q,k,v,o)

// k-permutation within each 16-group: slot(k) = 4(k&3) + 2((k>>3)&1) + ((k>>2)&1)
__device__ __forceinline__ int perm16(int k) {
    return 4 * (k & 3) + 2 * ((k >> 3) & 1) + ((k >> 2) & 1);
}

// ---------------------------------------------------------------------------
// tf32 + cp.async helpers (baseline PTX — compiles at target sm_103)
// ---------------------------------------------------------------------------
__device__ __forceinline__ uint32_t f2t(float x) {
    uint32_t r;
    asm("cvt.rna.tf32.f32 %0, %1;" : "=r"(r) : "f"(x));
    return r;
}
__device__ __forceinline__ float f2tf(float x) { return __uint_as_float(f2t(x)); }

__device__ __forceinline__ void mma8(float* c, uint32_t a0, uint32_t a1,
                                     uint32_t a2, uint32_t a3, uint32_t b0,
                                     uint32_t b1) {
    asm volatile(
        "mma.sync.aligned.m16n8k8.row.col.f32.tf32.tf32.f32 "
        "{%0,%1,%2,%3}, {%4,%5,%6,%7}, {%8,%9}, {%0,%1,%2,%3};"
        : "+f"(c[0]), "+f"(c[1]), "+f"(c[2]), "+f"(c[3])
        : "r"(a0), "r"(a1), "r"(a2), "r"(a3), "r"(b0), "r"(b1));
}
#define U(x) __float_as_uint(x)

__device__ __forceinline__ uint32_t smem_to_u32(const void* p) {
    uint32_t a;
    asm("{ .reg .u64 t; cvta.to.shared.u64 t, %1; cvt.u32.u64 %0, t; }"
        : "=r"(a) : "l"(p));
    return a;
}
__device__ __forceinline__ void cp16(uint32_t dst, const float* src) {
    asm volatile("cp.async.cg.shared.global [%0], [%1], 16;"
                 :: "r"(dst), "l"(src));
}
#define CP_COMMIT() asm volatile("cp.async.commit_group;" ::: "memory")
#define CP_WAIT0() asm volatile("cp.async.wait_group 0;" ::: "memory")
#define CP_WAIT1() asm volatile("cp.async.wait_group 1;" ::: "memory")

// ---------------------------------------------------------------------------
// Kernel: precompute interpolated relative bias per (h, rel)
// ---------------------------------------------------------------------------
__global__ void bias_kernel(const float* __restrict__ table,
                            const float* __restrict__ offset) {
    float bounded = tanhf(offset[0]) * 0.5f;
    for (int idx = blockIdx.x * blockDim.x + threadIdx.x; idx < Hc * NREL;
         idx += gridDim.x * blockDim.x) {
        int h = idx / NREL;
        int r = idx - h * NREL;
        float adj = (float)r + bounded;
        adj = fminf(fmaxf(adj, 0.0f), (float)(NREL - 1));
        int lo = (int)floorf(adj);
        int hi = (int)ceilf(adj);
        float w = adj - (float)lo;
        g_bias[h * NREL + r] =
            table[lo * Hc + h] * (1.0f - w) + table[hi * Hc + h] * w;
    }
}

// ---------------------------------------------------------------------------
// Conversion: tf32-round + 4x4 transpose within each 16-k group.
// One float4 then carries a thread's fragment elems for two k-groups.
// ---------------------------------------------------------------------------
__device__ __forceinline__ void round_perm16(const float4* in, float4* out) {
    float4 x0 = in[0], x1 = in[1], x2 = in[2], x3 = in[3];
    out[0] = {f2tf(x0.x), f2tf(x1.x), f2tf(x2.x), f2tf(x3.x)};
    out[1] = {f2tf(x0.y), f2tf(x1.y), f2tf(x2.y), f2tf(x3.y)};
    out[2] = {f2tf(x0.z), f2tf(x1.z), f2tf(x2.z), f2tf(x3.z)};
    out[3] = {f2tf(x0.w), f2tf(x1.w), f2tf(x2.w), f2tf(x3.w)};
}

__global__ void conv_perm3(const float* __restrict__ s0,
                           const float* __restrict__ s1,
                           const float* __restrict__ s2) {
    const int n16 = Mc * Ec / 16;
    for (int idx = blockIdx.x * blockDim.x + threadIdx.x; idx < 3 * n16;
         idx += gridDim.x * blockDim.x) {
        int a = idx / n16, r = idx - a * n16;
        const float* s = (a == 0) ? s0 : ((a == 1) ? s1 : s2);
        float4 o[4];
        round_perm16((const float4*)(s + (size_t)r * 16), o);
        float4* d = (float4*)(g_ar + (size_t)a * (Mc * Ec) + (size_t)r * 16);
        d[0] = o[0]; d[1] = o[1]; d[2] = o[2]; d[3] = o[3];
    }
}

__global__ void conv_perm4(const float* __restrict__ s0,
                           const float* __restrict__ s1,
                           const float* __restrict__ s2,
                           const float* __restrict__ s3) {
    const int n16 = Ec * Ec / 16;
    for (int idx = blockIdx.x * blockDim.x + threadIdx.x; idx < 4 * n16;
         idx += gridDim.x * blockDim.x) {
        int a = idx / n16, r = idx - a * n16;
        const float* s = (a == 0) ? s0 : ((a == 1) ? s1 : ((a == 2) ? s2 : s3));
        float4 o[4];
        round_perm16((const float4*)(s + (size_t)r * 16), o);
        float4* d = (float4*)(g_wr + (size_t)a * (Ec * Ec) + (size_t)r * 16);
        d[0] = o[0]; d[1] = o[1]; d[2] = o[2]; d[3] = o[3];
    }
}

// ---------------------------------------------------------------------------
// tf32 mma.sync GEMM v3: 3-stage cp.async, LDS.128 frags, XOR-swizzled smem.
// C[M,N] = A[M,K] * W[N,K]^T + bias[N].  CTA 128x128, 8 warps (4m x 2n).
// Rows of 32 floats (KC), 16B units swizzled: unit ^= (row&1)<<2.
// OUT_QKV: z = blockIdx.z -> (slice, bias, dst); Q/K stored d-permuted+rounded.
// IN_HEADS: A gathered from g_ao (already rounded+permuted).
// ---------------------------------------------------------------------------
#define KC 32
#define NCH (Ec / KC)            // 32
#define STG_F (128 * 32)         // 4096 floats per operand per stage
#define STAGE_F (2 * STG_F)      // 8192 floats per stage
#define NSTAGE 3
#define SMEM_GEMM (NSTAGE * STAGE_F * 4)  // 98304 B

template <int IN_HEADS, int OUT_QKV>
__global__ __launch_bounds__(256, 2) void gemm_tc(
    const float* __restrict__ bias0, const float* __restrict__ bias1,
    const float* __restrict__ bias2, float* __restrict__ Cplain) {
    extern __shared__ float sm[];
    const uint32_t smb = smem_to_u32(sm);

    const int tid = threadIdx.x;
    const int m0 = blockIdx.y * 128;
    const int n0 = blockIdx.x * 128;
    const int z = OUT_QKV ? blockIdx.z : 3;  // W slot 3 = Wo
    const int wid = tid >> 5, lane = tid & 31;
    const int wm = wid & 3, wn = wid >> 2;
    const int q = lane & 3, g = lane >> 2;

    const float* bias =
        OUT_QKV ? (z == 0 ? bias0 : (z == 1 ? bias1 : bias2)) : bias0;

    const int lr = tid >> 1;           // smem row this thread fills
    const int u0 = (tid & 1) * 4;      // first 16B unit
    const int usw_b = (lr & 1) << 2;   // fill-side swizzle bit

    const float* Wrow =
        g_wr + (size_t)z * (Ec * Ec) + (size_t)(n0 + lr) * Ec + u0 * 4;
    const float* Arow =
        IN_HEADS ? nullptr
                 : g_ar + (size_t)z * (Mc * Ec) + (size_t)(m0 + lr) * Ec + u0 * 4;

    auto fill = [&](int kt, int st) {
        uint32_t dA = smb + (uint32_t)(st * STAGE_F + lr * 32) * 4u;
        uint32_t dW = dA + STG_F * 4u;
        const float* sA;
        if (IN_HEADS) {
            int m = m0 + lr, bb = m >> 10, t = m & 1023;
            int e = kt * KC + u0 * 4, h = e >> 6, d = e & 63;
            sA = g_ao + (((size_t)(bb * Hc + h) * Tc + t) * Dc + d);
        } else {
            sA = Arow + kt * KC;
        }
        const float* sW = Wrow + kt * KC;
#pragma unroll
        for (int i = 0; i < 4; i++) {
            uint32_t uo = (uint32_t)(((u0 + i) ^ usw_b) << 4);
            cp16(dA + uo, sA + 4 * i);
            cp16(dW + uo, sW + 4 * i);
        }
    };

    float acc[2][8][4];
#pragma unroll
    for (int f = 0; f < 2; f++)
#pragma unroll
        for (int j = 0; j < 8; j++)
#pragma unroll
            for (int v = 0; v < 4; v++) acc[f][j][v] = 0.0f;

    fill(0, 0);
    CP_COMMIT();
    fill(1, 1);
    CP_COMMIT();

    const int swz = (g & 1) << 2;  // consume-side swizzle bit
    for (int kt = 0; kt < NCH; kt++) {
        const int st = kt % NSTAGE;
        CP_WAIT1();
        __syncthreads();
        if (kt + 2 < NCH) fill(kt + 2, (kt + 2) % NSTAGE);
        CP_COMMIT();

        const float* As = sm + st * STAGE_F;
        const float* Ws = As + STG_F;
#pragma unroll
        for (int kp = 0; kp < 2; kp++) {
            const int uo = ((4 * kp + q) ^ swz) * 4;
            float4 a[2][2];
#pragma unroll
            for (int f = 0; f < 2; f++) {
                const float* ap = As + (wm * 32 + f * 16 + g) * 32 + uo;
                a[f][0] = *(const float4*)ap;
                a[f][1] = *(const float4*)(ap + 8 * 32);
            }
#pragma unroll
            for (int j = 0; j < 8; j++) {
                const float* bp = Ws + (wn * 64 + j * 8 + g) * 32 + uo;
                float4 b = *(const float4*)bp;
                mma8(acc[0][j], U(a[0][0].x), U(a[0][1].x), U(a[0][0].y),
                     U(a[0][1].y), U(b.x), U(b.y));
                mma8(acc[1][j], U(a[1][0].x), U(a[1][1].x), U(a[1][0].y),
                     U(a[1][1].y), U(b.x), U(b.y));
                mma8(acc[0][j], U(a[0][0].z), U(a[0][1].z), U(a[0][0].w),
                     U(a[0][1].w), U(b.z), U(b.w));
                mma8(acc[1][j], U(a[1][0].z), U(a[1][1].z), U(a[1][0].w),
                     U(a[1][1].w), U(b.z), U(b.w));
            }
        }
    }

    // Epilogue: row = wm*32 + f*16 + rr*8 + g, col = wn*64 + j*8 + 2q + {0,1}
#pragma unroll
    for (int f = 0; f < 2; f++) {
#pragma unroll
        for (int rr = 0; rr < 2; rr++) {
            int m = m0 + wm * 32 + f * 16 + rr * 8 + g;
#pragma unroll
            for (int j = 0; j < 8; j++) {
                int n = n0 + wn * 64 + j * 8 + 2 * q;
                float vx = acc[f][j][rr * 2 + 0] + __ldg(bias + n);
                float vy = acc[f][j][rr * 2 + 1] + __ldg(bias + n + 1);
                if (OUT_QKV) {
                    float* C = (z == 0) ? g_q : ((z == 1) ? g_k : g_v);
                    int bb = m >> 10, t = m & 1023;
                    int h = n >> 6;
                    float* dst = C + ((size_t)(bb * Hc + h) * Tc + t) * Dc;
                    int d = n & 63;
                    if (z < 2) {  // d-permuted for attention fragment loads
                        dst[(d & ~15) + perm16(d & 15)] = f2tf(vx);
                        dst[((d + 1) & ~15) + perm16((d + 1) & 15)] = f2tf(vy);
                    } else {
                        float2 v = {f2tf(vx), f2tf(vy)};
                        *(float2*)(dst + d) = v;
                    }
                } else {
                    float2 v = {vx, vy};
                    *(float2*)(Cplain + (size_t)m * Ec + n) = v;
                }
            }
        }
    }
}

// ---------------------------------------------------------------------------
// Fused attention v3: Q/K in swizzled 64-float rows (d pre-permuted ->
// LDS.128 fragment loads), V stride 72 row-major, double-buffered K/V via
// cp.async, bias window staged once.  8 warps x 16 q-rows, softmax warp-local.
// Output stored rounded + k-permuted into g_ao for the Wo GEMM.
// ---------------------------------------------------------------------------
#define OQ 0
#define OK0 (128 * 64)           // 8192
#define OK1 (OK0 + 64 * 64)      // 12288
#define OV0 (OK1 + 64 * 64)      // 16384
#define OV1 (OV0 + 64 * 72)      // 20992
#define OSB (OV1 + 64 * 72)      // 25600
#define SMEM_ATTN ((OSB + 1152) * 4)  // 107008 B

__global__ __launch_bounds__(256, 2) void attn_tc() {
    extern __shared__ float sm[];
    const uint32_t smb = smem_to_u32(sm);
    float* sb = sm + OSB;

    const int tid = threadIdx.x, wid = tid >> 5, lane = tid & 31;
    const int q = lane & 3, g = lane >> 2;
    const int bh = blockIdx.y;
    const int q0 = blockIdx.x * 128;
    const int h = bh & (Hc - 1);

    const float* Qg = g_q + ((size_t)bh * Tc + q0) * Dc;
    const float* Kg = g_k + (size_t)bh * Tc * Dc;
    const float* Vg = g_v + (size_t)bh * Tc * Dc;
    const float scale = 0.125f;

    auto fillKV = [&](int kt, int p) {
        int row = tid >> 2, uq = tid & 3;
        uint32_t dK = smb + (uint32_t)((p ? OK1 : OK0) + row * 64) * 4u;
        uint32_t dV =
            smb + (uint32_t)((p ? OV1 : OV0) + row * 72 + uq * 16) * 4u;
        const float* sK = Kg + (size_t)(kt * 64 + row) * 64;
        const float* sV = Vg + (size_t)(kt * 64 + row) * 64 + uq * 16;
        int swb = (row & 1) << 2;
#pragma unroll
        for (int i = 0; i < 4; i++) {
            int u = uq * 4 + i;
            cp16(dK + (uint32_t)((u ^ swb) << 4), sK + u * 4);
            cp16(dV + 16u * i, sV + 4 * i);
        }
    };

    // prologue: Q + KV chunk 0, bias window
    {
        int row = tid >> 1, uh = tid & 1;
        uint32_t dQ = smb + (uint32_t)(OQ + row * 64) * 4u;
        const float* sQ = Qg + row * 64;
        int swb = (row & 1) << 2;
#pragma unroll
        for (int i = 0; i < 8; i++) {
            int u = uh * 8 + i;
            cp16(dQ + (uint32_t)((u ^ swb) << 4), sQ + u * 4);
        }
    }
    fillKV(0, 0);
    CP_COMMIT();
    for (int i = tid; i < 1151; i += 256) sb[i] = g_bias[h * NREL + q0 + i];

    const int r0 = wid * 16 + g;
    float m_[2] = {-1e30f, -1e30f}, l_[2] = {0.0f, 0.0f};
    float O[8][4];
#pragma unroll
    for (int j = 0; j < 8; j++)
#pragma unroll
        for (int v = 0; v < 4; v++) O[j][v] = 0.0f;

    const int swz = (g & 1) << 2;
    for (int kt = 0; kt < Tc / 64; kt++) {
        const int p = kt & 1;
        CP_WAIT0();
        __syncthreads();
        if (kt + 1 < Tc / 64) fillKV(kt + 1, p ^ 1);
        CP_COMMIT();

        const float* Ks = sm + (p ? OK1 : OK0);
        const float* Vs = sm + (p ? OV1 : OV0);

        // phase A: S = Q K^T (warp tile 16 x 64), LDS.128 fragments
        float s[8][4];
#pragma unroll
        for (int j = 0; j < 8; j++)
#pragma unroll
            for (int v = 0; v < 4; v++) s[j][v] = 0.0f;
#pragma unroll
        for (int kp = 0; kp < 4; kp++) {
            const int uo = ((4 * kp + q) ^ swz) * 4;
            const float* ap = sm + OQ + (wid * 16 + g) * 64 + uo;
            float4 alo = *(const float4*)ap;
            float4 ahi = *(const float4*)(ap + 8 * 64);
#pragma unroll
            for (int j = 0; j < 8; j++) {
                const float* bp = Ks + (j * 8 + g) * 64 + uo;
                float4 b = *(const float4*)bp;
                mma8(s[j], U(alo.x), U(ahi.x), U(alo.y), U(ahi.y), U(b.x),
                     U(b.y));
                mma8(s[j], U(alo.z), U(ahi.z), U(alo.w), U(ahi.w), U(b.z),
                     U(b.w));
            }
        }

        // scale + bias, row maxima
        float mx0 = -1e30f, mx1 = -1e30f;
#pragma unroll
        for (int j = 0; j < 8; j++) {
            int i0 = r0 - kt * 64 - (j * 8 + 2 * q) + 1023;
            s[j][0] = s[j][0] * scale + sb[i0];
            s[j][1] = s[j][1] * scale + sb[i0 - 1];
            s[j][2] = s[j][2] * scale + sb[i0 + 8];
            s[j][3] = s[j][3] * scale + sb[i0 + 7];
            mx0 = fmaxf(mx0, fmaxf(s[j][0], s[j][1]));
            mx1 = fmaxf(mx1, fmaxf(s[j][2], s[j][3]));
        }
        mx0 = fmaxf(mx0, __shfl_xor_sync(0xffffffffu, mx0, 1));
        mx0 = fmaxf(mx0, __shfl_xor_sync(0xffffffffu, mx0, 2));
        mx1 = fmaxf(mx1, __shfl_xor_sync(0xffffffffu, mx1, 1));
        mx1 = fmaxf(mx1, __shfl_xor_sync(0xffffffffu, mx1, 2));

        float mn0 = fmaxf(m_[0], mx0), mn1 = fmaxf(m_[1], mx1);
        float corr0 = __expf(m_[0] - mn0), corr1 = __expf(m_[1] - mn1);
        float sum0 = 0.0f, sum1 = 0.0f;
#pragma unroll
        for (int j = 0; j < 8; j++) {
            s[j][0] = __expf(s[j][0] - mn0);
            s[j][1] = __expf(s[j][1] - mn0);
            s[j][2] = __expf(s[j][2] - mn1);
            s[j][3] = __expf(s[j][3] - mn1);
            sum0 += s[j][0] + s[j][1];
            sum1 += s[j][2] + s[j][3];
        }
        sum0 += __shfl_xor_sync(0xffffffffu, sum0, 1);
        sum0 += __shfl_xor_sync(0xffffffffu, sum0, 2);
        sum1 += __shfl_xor_sync(0xffffffffu, sum1, 1);
        sum1 += __shfl_xor_sync(0xffffffffu, sum1, 2);
        l_[0] = l_[0] * corr0 + sum0;
        l_[1] = l_[1] * corr1 + sum1;
        m_[0] = mn0;
        m_[1] = mn1;
#pragma unroll
        for (int j = 0; j < 8; j++) {
            O[j][0] *= corr0; O[j][1] *= corr0;
            O[j][2] *= corr1; O[j][3] *= corr1;
        }

        // phase B: O += P V (P via shuffles; V row-major stride 72)
        const int base = lane & ~3;
        const int s0l = base + (q >> 1);
        const int s1l = base + 2 + (q >> 1);
        const bool odd = (q & 1);
#pragma unroll
        for (int j = 0; j < 8; j++) {
            float t00 = __shfl_sync(0xffffffffu, s[j][0], s0l);
            float t01 = __shfl_sync(0xffffffffu, s[j][1], s0l);
            float t10 = __shfl_sync(0xffffffffu, s[j][0], s1l);
            float t11 = __shfl_sync(0xffffffffu, s[j][1], s1l);
            float t20 = __shfl_sync(0xffffffffu, s[j][2], s0l);
            float t21 = __shfl_sync(0xffffffffu, s[j][3], s0l);
            float t30 = __shfl_sync(0xffffffffu, s[j][2], s1l);
            float t31 = __shfl_sync(0xffffffffu, s[j][3], s1l);
            uint32_t a0 = f2t(odd ? t01 : t00);
            uint32_t a1 = f2t(odd ? t21 : t20);
            uint32_t a2 = f2t(odd ? t11 : t10);
            uint32_t a3 = f2t(odd ? t31 : t30);
#pragma unroll
            for (int n = 0; n < 8; n++) {
                const float* bp0 = Vs + (j * 8 + q) * 72 + n * 8 + g;
                const float* bp1 = Vs + (j * 8 + q + 4) * 72 + n * 8 + g;
                mma8(O[n], a0, a1, a2, a3, U(*bp0), U(*bp1));
            }
        }
    }

    // normalize + store rounded & k-permuted into g_ao (for the Wo GEMM)
    float inv0 = 1.0f / l_[0], inv1 = 1.0f / l_[1];
    float* Og = g_ao + ((size_t)bh * Tc + q0 + wid * 16) * Dc;
#pragma unroll
    for (int j = 0; j < 8; j++) {
        int d0 = j * 8 + 2 * q, d1 = d0 + 1;
        int p0 = (d0 & ~15) + perm16(d0 & 15);
        int p1 = (d1 & ~15) + perm16(d1 & 15);
        Og[g * 64 + p0] = f2tf(O[j][0] * inv0);
        Og[g * 64 + p1] = f2tf(O[j][1] * inv0);
        Og[(g + 8) * 64 + p0] = f2tf(O[j][2] * inv1);
        Og[(g + 8) * 64 + p1] = f2tf(O[j][3] * inv1);
    }
}

// ---------------------------------------------------------------------------
extern "C" void kernel_launch(void* const* d_in, const int* in_sizes, int n_in,
                              void* d_out, int out_size) {
    (void)in_sizes; (void)n_in; (void)out_size;
    const float* query = (const float*)d_in[0];
    const float* key_ = (const float*)d_in[1];
    const float* value = (const float*)d_in[2];
    const float* Wq = (const float*)d_in[3];
    const float* bq = (const float*)d_in[4];
    const float* Wk = (const float*)d_in[5];
    const float* bk = (const float*)d_in[6];
    const float* Wv = (const float*)d_in[7];
    const float* bv = (const float*)d_in[8];
    const float* Wo = (const float*)d_in[9];
    const float* bo = (const float*)d_in[10];
    const float* bias_table = (const float*)d_in[11];
    const float* offset = (const float*)d_in[12];
    float* out = (float*)d_out;

    cudaFuncSetAttribute(gemm_tc<0, 1>,
                         cudaFuncAttributeMaxDynamicSharedMemorySize, SMEM_GEMM);
    cudaFuncSetAttribute(gemm_tc<1, 0>,
                         cudaFuncAttributeMaxDynamicSharedMemorySize, SMEM_GEMM);
    cudaFuncSetAttribute(attn_tc, cudaFuncAttributeMaxDynamicSharedMemorySize,
                         SMEM_ATTN);

    bias_kernel<<<32, 256>>>(bias_table, offset);
    conv_perm3<<<2048, 256>>>(query, key_, value);
    conv_perm4<<<1024, 256>>>(Wq, Wk, Wv, Wo);

    dim3 ggrid(Ec / 128, Mc / 128, 3);  // QKV fused: (8, 64, 3)
    gemm_tc<0, 1><<<ggrid, 256, SMEM_GEMM>>>(bq, bk, bv, nullptr);

    dim3 agrid(Tc / 128, Bc * Hc);  // (8, 128)
    attn_tc<<<agrid, 256, SMEM_ATTN>>>();

    dim3 ogrid(Ec / 128, Mc / 128, 1);
    gemm_tc<1, 0><<<ogrid, 256, SMEM_GEMM>>>(bo, nullptr, nullptr, out);
}